// round 6
// baseline (speedup 1.0000x reference)
#include <cuda_runtime.h>
#include <cuda_fp16.h>
#include <cstdint>
#include <cstddef>

#define B_   32
#define T_   2048
#define D_   1024
#define U_   1024
#define MTOT (B_ * T_)   // 65536

#define BM 128
#define BN 128
#define BK 32            // halfs per k-stage
#define NCH (D_ / BK)    // 32 k-chunks
#define STAGES 4

// smem (32-bit words): A[stage][128 rows][20], B[stage][128 rows][20]
#define AROW_W 20
#define STAGE_W (128 * AROW_W)                 // 2560 words per tile
#define SM_B_OFF_W (STAGES * STAGE_W)          // 10240
#define SM_RED_W   (2 * STAGES * STAGE_W)      // 20480
#define SMEM_WORDS (SM_RED_W + BM * 4)
#define SMEM_BYTES (SMEM_WORDS * 4)            // 84 KB

// Scratch (no cudaMalloc allowed): device globals
__device__ float g_qp[B_ * U_];                 // q_proj + b1 + b2
__device__ float g_qpp[8 * B_ * U_];            // qproj d-chunk partials
__device__ uint4 g_vh4[MTOT * D_ / 8];          // values fp16 [b,t,d]
__device__ uint4 g_w2h4[U_ * D_ / 8];           // W2^T fp16 [u][d]
__device__ float g_part[8 * MTOT];              // score partials per N-slab
__device__ float g_ctxp[16 * B_ * D_];          // context partials per t-chunk

// ---------------------------------------------------------------------------
__device__ __forceinline__ uint32_t smem_u32(const void* p) {
    uint32_t a;
    asm("{ .reg .u64 t; cvta.to.shared.u64 t, %1; cvt.u32.u64 %0, t; }" : "=r"(a) : "l"(p));
    return a;
}

__device__ __forceinline__ void cpa16(uint32_t dst, const void* src) {
    asm volatile("cp.async.cg.shared.global [%0], [%1], 16;" :: "r"(dst), "l"(src));
}

__device__ __forceinline__ void ldmx4(uint32_t r[4], uint32_t addr) {
    asm volatile("ldmatrix.sync.aligned.m8n8.x4.shared.b16 {%0,%1,%2,%3}, [%4];"
                 : "=r"(r[0]), "=r"(r[1]), "=r"(r[2]), "=r"(r[3]) : "r"(addr));
}

__device__ __forceinline__ void mma_f16(float d[4], const uint32_t a[4], const uint32_t b[2]) {
    asm volatile(
        "mma.sync.aligned.m16n8k16.row.col.f32.f16.f16.f32 "
        "{%0,%1,%2,%3}, {%4,%5,%6,%7}, {%8,%9}, {%0,%1,%2,%3};\n"
        : "+f"(d[0]), "+f"(d[1]), "+f"(d[2]), "+f"(d[3])
        : "r"(a[0]), "r"(a[1]), "r"(a[2]), "r"(a[3]),
          "r"(b[0]), "r"(b[1]));
}

// ---------------------------------------------------------------------------
// K_A (launch 1): fused { qproj partials | W2 transpose+fp16 }.
// blocks [0,32): qproj — bu = bid&3 (256-u slab), bd = bid>>2 (128-d chunk).
// blocks [32,1056): W2 [d][u] -> fp16 W2^T [u][d], 32x32 tiles.
// ---------------------------------------------------------------------------
__global__ void fusedA_kernel(const float* __restrict__ query,
                              const float* __restrict__ W1,
                              const float* __restrict__ W2) {
    __shared__ float smf[32 * 128];
    const int tid = threadIdx.x;
    if (blockIdx.x < 32) {
        const int u  = (blockIdx.x & 3) * 256 + tid;
        const int cd = blockIdx.x >> 2;
        const int d0 = cd * 128;
        // smf = qT[d][b] (transposed query chunk)
        for (int i = tid; i < 32 * 128; i += 256) {
            const int d = i >> 5, b = i & 31;
            smf[d * 32 + b] = query[b * D_ + d0 + d];
        }
        __syncthreads();
        float acc[32];
#pragma unroll
        for (int b = 0; b < 32; ++b) acc[b] = 0.f;
        for (int d = 0; d < 128; ++d) {
            const float w = W1[(size_t)(d0 + d) * U_ + u];
            const float4* q4 = (const float4*)&smf[d * 32];
#pragma unroll
            for (int b4 = 0; b4 < 8; ++b4) {
                const float4 q = q4[b4];
                acc[b4 * 4 + 0] = fmaf(q.x, w, acc[b4 * 4 + 0]);
                acc[b4 * 4 + 1] = fmaf(q.y, w, acc[b4 * 4 + 1]);
                acc[b4 * 4 + 2] = fmaf(q.z, w, acc[b4 * 4 + 2]);
                acc[b4 * 4 + 3] = fmaf(q.w, w, acc[b4 * 4 + 3]);
            }
        }
#pragma unroll
        for (int b = 0; b < 32; ++b)
            g_qpp[cd * (B_ * U_) + b * U_ + u] = acc[b];
    } else {
        const int bid = blockIdx.x - 32;           // 0..1023
        const int u0 = (bid & 31) * 32, d0 = (bid >> 5) * 32;
        const int tx = tid & 31, ty = tid >> 5;    // (32, 8)
        float (*tile)[33] = (float(*)[33])smf;
        __half* w2h = (__half*)g_w2h4;
#pragma unroll
        for (int i = 0; i < 32; i += 8)
            tile[ty + i][tx] = W2[(size_t)(d0 + ty + i) * U_ + u0 + tx];
        __syncthreads();
#pragma unroll
        for (int i = 0; i < 32; i += 8)
            w2h[(size_t)(u0 + ty + i) * D_ + d0 + tx] = __float2half_rn(tile[tx][ty + i]);
    }
}

// K_B (launch 2): qproj reduce + biases. grid 128 x 256.
__global__ void qproj_red_kernel(const float* __restrict__ b1,
                                 const float* __restrict__ b2) {
    const int i = blockIdx.x * 256 + threadIdx.x;   // < 32768
    const int u = i & (U_ - 1);
    float s = b1[u] + b2[u];
#pragma unroll
    for (int k = 0; k < 8; ++k) s += g_qpp[k * (B_ * U_) + i];
    g_qp[i] = s;
}

// K_C (launch 3): values fp32 -> fp16. grid 32768 x 256, 8 elems/thread.
__global__ void cvt_vals_kernel(const float4* __restrict__ v) {
    const size_t i = (size_t)blockIdx.x * 256 + threadIdx.x;
    const float4 a = v[2 * i], b = v[2 * i + 1];
    const __half2 h0 = __floats2half2_rn(a.x, a.y);
    const __half2 h1 = __floats2half2_rn(a.z, a.w);
    const __half2 h2 = __floats2half2_rn(b.x, b.y);
    const __half2 h3 = __floats2half2_rn(b.z, b.w);
    uint4 o;
    o.x = *(const uint32_t*)&h0; o.y = *(const uint32_t*)&h1;
    o.z = *(const uint32_t*)&h2; o.w = *(const uint32_t*)&h3;
    g_vh4[i] = o;
}

// ---------------------------------------------------------------------------
// K_D (launch 4 -> ncu target): fused fp16 GEMM + tanh/Wv score.
// CTA 128x128, BK=32, 4-stage cp.async, 8 warps (2x4), warp 64x32,
// LDSM.x4 fragment loads, 4x4 m16n8k16 f16 mma w/ fp32 accum.
// grid (8, 512) x 256. Deterministic (no atomics).
// ---------------------------------------------------------------------------
__global__ __launch_bounds__(256, 2)
void gemm_score_kernel(const float* __restrict__ Wv) {
    extern __shared__ float sm[];
    float* Red = sm + SM_RED_W;
    const uint32_t sbA = smem_u32(sm);
    const uint32_t sbB = sbA + SM_B_OFF_W * 4;

    const int tid   = threadIdx.x;
    const int lane  = tid & 31;
    const int warp  = tid >> 5;
    const int warpM = warp >> 2;
    const int warpN = warp & 3;
    const int gid   = lane >> 2;
    const int tig   = lane & 3;
    const int bN      = blockIdx.x;
    const int rowBase = blockIdx.y * BM;

    const __half* Vh  = (const __half*)g_vh4;
    const __half* W2h = (const __half*)g_w2h4;

    // producer: 2 A-chunks + 2 B-chunks (16B) per thread per stage
    const int cA0r = tid >> 2,         cA0w = (tid & 3) * 4;
    const int cA1r = (tid + 256) >> 2, cA1w = ((tid + 256) & 3) * 4;

    const __half* gA0 = Vh  + (size_t)(rowBase + cA0r) * D_ + cA0w * 2;
    const __half* gA1 = Vh  + (size_t)(rowBase + cA1r) * D_ + cA1w * 2;
    const __half* gB0 = W2h + (size_t)(bN * BN + cA0r) * D_ + cA0w * 2;
    const __half* gB1 = W2h + (size_t)(bN * BN + cA1r) * D_ + cA1w * 2;

    const uint32_t dA0 = sbA + (cA0r * AROW_W + cA0w) * 4;
    const uint32_t dA1 = sbA + (cA1r * AROW_W + cA1w) * 4;
    const uint32_t dB0 = sbB + (cA0r * AROW_W + cA0w) * 4;
    const uint32_t dB1 = sbB + (cA1r * AROW_W + cA1w) * 4;
    const uint32_t stg = STAGE_W * 4;   // stage stride bytes

    // LDSM lane addressing (stage-invariant bases)
    // A: lanes 0-15 -> rows m0+0..15 k-words +0; lanes 16-31 -> same rows, +4
    const uint32_t aLdm = sbA + (((warpM * 64 + (lane & 15)) * AROW_W)
                                 + ((lane & 16) ? 4 : 0)) * 4;
    // B: lanes {0-7,8-15} rows n0+0..7 words {+0,+4}; lanes {16-23,24-31} rows +8
    const uint32_t bLdm = sbB + (((warpN * 32 + (lane & 7) + ((lane & 16) ? 8 : 0)) * AROW_W)
                                 + ((lane & 8) ? 4 : 0)) * 4;

    float acc[4][4][4];
#pragma unroll
    for (int i = 0; i < 4; ++i)
#pragma unroll
        for (int j = 0; j < 4; ++j)
#pragma unroll
            for (int k = 0; k < 4; ++k) acc[i][j][k] = 0.f;

#pragma unroll
    for (int p = 0; p < STAGES - 1; ++p) {
        cpa16(dA0 + p * stg, gA0 + p * BK);
        cpa16(dA1 + p * stg, gA1 + p * BK);
        cpa16(dB0 + p * stg, gB0 + p * BK);
        cpa16(dB1 + p * stg, gB1 + p * BK);
        asm volatile("cp.async.commit_group;" ::: "memory");
    }

    for (int kc = 0; kc < NCH; ++kc) {
        asm volatile("cp.async.wait_group %0;" :: "n"(STAGES - 2) : "memory");
        __syncthreads();

        if (kc + STAGES - 1 < NCH) {
            const int p = kc + STAGES - 1;
            const int s2 = p & (STAGES - 1);
            cpa16(dA0 + s2 * stg, gA0 + p * BK);
            cpa16(dA1 + s2 * stg, gA1 + p * BK);
            cpa16(dB0 + s2 * stg, gB0 + p * BK);
            cpa16(dB1 + s2 * stg, gB1 + p * BK);
        }
        asm volatile("cp.async.commit_group;" ::: "memory");

        const int s = kc & (STAGES - 1);
        const uint32_t aS = aLdm + s * stg;
        const uint32_t bS = bLdm + s * stg;
#pragma unroll
        for (int ks = 0; ks < 2; ++ks) {
            const uint32_t ko = ks * 32;     // 8 words = 32 bytes
            uint32_t af[4][4];
#pragma unroll
            for (int mt = 0; mt < 4; ++mt)
                ldmx4(af[mt], aS + mt * (16 * AROW_W * 4) + ko);
            uint32_t bf[4][2];
            {
                uint32_t r[4];
                ldmx4(r, bS + ko);
                bf[0][0] = r[0]; bf[0][1] = r[1]; bf[1][0] = r[2]; bf[1][1] = r[3];
                ldmx4(r, bS + 16 * AROW_W * 4 + ko);
                bf[2][0] = r[0]; bf[2][1] = r[1]; bf[3][0] = r[2]; bf[3][1] = r[3];
            }
#pragma unroll
            for (int mt = 0; mt < 4; ++mt)
#pragma unroll
                for (int nt = 0; nt < 4; ++nt)
                    mma_f16(acc[mt][nt], af[mt], bf[nt]);
        }
    }

    // ---- fused epilogue: tanh + dot(Wv) -> per-row partial scores ----
    const int b = rowBase >> 11;   // 128 | 2048, tiles never straddle a batch
    float qv[4][2], wvv[4][2];
#pragma unroll
    for (int nt = 0; nt < 4; ++nt)
#pragma unroll
        for (int j = 0; j < 2; ++j) {
            const int n = bN * BN + warpN * 32 + nt * 8 + tig * 2 + j;
            qv[nt][j]  = g_qp[b * U_ + n];
            wvv[nt][j] = Wv[n];
        }
#pragma unroll
    for (int mt = 0; mt < 4; ++mt) {
        float s0 = 0.f, s1 = 0.f;
#pragma unroll
        for (int nt = 0; nt < 4; ++nt) {
            s0 += tanhf(acc[mt][nt][0] + qv[nt][0]) * wvv[nt][0];
            s0 += tanhf(acc[mt][nt][1] + qv[nt][1]) * wvv[nt][1];
            s1 += tanhf(acc[mt][nt][2] + qv[nt][0]) * wvv[nt][0];
            s1 += tanhf(acc[mt][nt][3] + qv[nt][1]) * wvv[nt][1];
        }
        s0 += __shfl_xor_sync(0xffffffffu, s0, 1);
        s0 += __shfl_xor_sync(0xffffffffu, s0, 2);
        s1 += __shfl_xor_sync(0xffffffffu, s1, 1);
        s1 += __shfl_xor_sync(0xffffffffu, s1, 2);
        if (tig == 0) {
            const int rl = warpM * 64 + mt * 16 + gid;
            Red[rl * 4 + warpN]       = s0;
            Red[(rl + 8) * 4 + warpN] = s1;
        }
    }
    __syncthreads();
    if (tid < BM) {
        const float s = Red[tid * 4] + Red[tid * 4 + 1] + Red[tid * 4 + 2] + Red[tid * 4 + 3];
        g_part[bN * MTOT + rowBase + tid] = s;
    }
}

// ---------------------------------------------------------------------------
// K_E: per-batch softmax over T=2048. grid 32 x 256. bv cancels.
// ---------------------------------------------------------------------------
__global__ void softmax_kernel(float* __restrict__ out_w) {
    const int b = blockIdx.x;
    const int tid = threadIdx.x;
    __shared__ float red[256];
    const int base = b * T_;
    float sc[8];
#pragma unroll
    for (int i = 0; i < 8; ++i) {
        const int t = tid + i * 256;
        float s = 0.f;
#pragma unroll
        for (int p = 0; p < 8; ++p) s += g_part[p * MTOT + base + t];
        sc[i] = s;
    }
    float m = sc[0];
#pragma unroll
    for (int i = 1; i < 8; ++i) m = fmaxf(m, sc[i]);
    red[tid] = m;
    __syncthreads();
    for (int off = 128; off > 0; off >>= 1) {
        if (tid < off) red[tid] = fmaxf(red[tid], red[tid + off]);
        __syncthreads();
    }
    m = red[0];
    __syncthreads();
    float sum = 0.f;
#pragma unroll
    for (int i = 0; i < 8; ++i) {
        sc[i] = expf(sc[i] - m);
        sum += sc[i];
    }
    red[tid] = sum;
    __syncthreads();
    for (int off = 128; off > 0; off >>= 1) {
        if (tid < off) red[tid] += red[tid + off];
        __syncthreads();
    }
    const float inv = 1.f / red[0];
#pragma unroll
    for (int i = 0; i < 8; ++i)
        out_w[base + tid + i * 256] = sc[i] * inv;
}

// ---------------------------------------------------------------------------
// K_F: partial context from fp16 values. grid (16, 32) x 256.
// ---------------------------------------------------------------------------
__global__ void ctx_partial_kernel(const float* __restrict__ w) {
    const int tc = blockIdx.x;
    const int b  = blockIdx.y;
    const int tid = threadIdx.x;
    __shared__ float ws[128];
    if (tid < 128) ws[tid] = w[b * T_ + tc * 128 + tid];
    __syncthreads();
    float4 acc = make_float4(0.f, 0.f, 0.f, 0.f);
    const uint2* vp = (const uint2*)g_vh4
                    + ((size_t)(b * T_ + tc * 128) * D_) / 4 + tid;
#pragma unroll 4
    for (int tt = 0; tt < 128; ++tt) {
        const float wv = ws[tt];
        const uint2 v = vp[(size_t)tt * 256];
        const float2 f0 = __half22float2(*(const __half2*)&v.x);
        const float2 f1 = __half22float2(*(const __half2*)&v.y);
        acc.x = fmaf(wv, f0.x, acc.x);
        acc.y = fmaf(wv, f0.y, acc.y);
        acc.z = fmaf(wv, f1.x, acc.z);
        acc.w = fmaf(wv, f1.y, acc.w);
    }
    *(float4*)&g_ctxp[(size_t)(tc * B_ + b) * D_ + tid * 4] = acc;
}

// K_G: reduce the 16 t-chunk partials. grid 128 x 256.
__global__ void ctx_reduce_kernel(float* __restrict__ out_ctx) {
    const int i = blockIdx.x * 256 + threadIdx.x;
    float s = 0.f;
#pragma unroll
    for (int tc = 0; tc < 16; ++tc) s += g_ctxp[tc * (B_ * D_) + i];
    out_ctx[i] = s;
}

// ---------------------------------------------------------------------------
extern "C" void kernel_launch(void* const* d_in, const int* in_sizes, int n_in,
                              void* d_out, int out_size) {
    const float* query  = (const float*)d_in[0];
    const float* values = (const float*)d_in[1];
    const float* W1     = (const float*)d_in[2];
    const float* b1     = (const float*)d_in[3];
    const float* W2     = (const float*)d_in[4];
    const float* b2     = (const float*)d_in[5];
    const float* Wv     = (const float*)d_in[6];
    // d_in[7] = bv: cancels in softmax (shift-invariant), unused.
    (void)in_sizes; (void)n_in; (void)out_size;

    float* out_ctx = (float*)d_out;            // [32,1024]
    float* out_w   = (float*)d_out + B_ * D_;  // [32,2048,1]

    static int smem_set = 0;
    if (!smem_set) {
        cudaFuncSetAttribute(gemm_score_kernel,
                             cudaFuncAttributeMaxDynamicSharedMemorySize, SMEM_BYTES);
        smem_set = 1;
    }

    fusedA_kernel<<<1056, 256>>>(query, W1, W2);             // 1: qproj part + W2^T
    qproj_red_kernel<<<128, 256>>>(b1, b2);                  // 2
    cvt_vals_kernel<<<MTOT * D_ / 8 / 256, 256>>>((const float4*)values); // 3
    gemm_score_kernel<<<dim3(8, 512), 256, SMEM_BYTES>>>(Wv);// 4 (ncu)
    softmax_kernel<<<32, 256>>>(out_w);                      // 5
    ctx_partial_kernel<<<dim3(16, 32), 256>>>(out_w);        // 6
    ctx_reduce_kernel<<<128, 256>>>(out_ctx);                // 7
}

// round 7
// speedup vs baseline: 1.3567x; 1.3567x over previous
#include <cuda_runtime.h>
#include <cuda_fp16.h>
#include <cstdint>
#include <cstddef>

#define B_   32
#define T_   2048
#define D_   1024
#define U_   1024
#define MTOT (B_ * T_)   // 65536

#define BM 128
#define BN 128
#define BK 64            // halfs (and floats) per k-stage
#define NCHUNK (D_ / BK) // 16 k-stages

// smem (32-bit words): per stage A[128][36] then B[128][36]
#define AROW_W 36                               // 32 data + 4 pad (conflict-free)
#define HALF_STAGE_W (128 * AROW_W)             // 4608 words (A or B)
#define STAGE_W (2 * HALF_STAGE_W)              // 9216 words
#define STG_BYTES (STAGE_W * 4)                 // 36864
#define SM_RED_W (2 * STAGE_W)                  // 18432
#define SMEM_BYTES ((SM_RED_W + BM * 4) * 4)    // 75776 B -> 2 CTAs/SM

// Scratch (no cudaMalloc allowed): device globals
__device__ float g_qp[B_ * U_];                 // q_proj + b1 + b2
__device__ float g_qpp[8 * B_ * U_];            // qproj d-chunk partials
__device__ uint4 g_w2h4[U_ * D_ / 8];           // W2^T fp16 [u][d]
__device__ float g_part[8 * MTOT];              // score partials per N-slab
__device__ float g_ctxp[8 * B_ * D_];           // context partials per t-chunk

// ---------------------------------------------------------------------------
__device__ __forceinline__ uint32_t smem_u32(const void* p) {
    uint32_t a;
    asm("{ .reg .u64 t; cvta.to.shared.u64 t, %1; cvt.u32.u64 %0, t; }" : "=r"(a) : "l"(p));
    return a;
}

__device__ __forceinline__ void cpa16(uint32_t dst, const void* src) {
    asm volatile("cp.async.cg.shared.global [%0], [%1], 16;" :: "r"(dst), "l"(src));
}

// convert float4 -> 4 halfs, store 8B to smem
__device__ __forceinline__ void sts_h4(uint32_t addr, float4 v) {
    const __half2 h0 = __floats2half2_rn(v.x, v.y);
    const __half2 h1 = __floats2half2_rn(v.z, v.w);
    asm volatile("st.shared.v2.b32 [%0], {%1,%2};"
                 :: "r"(addr), "r"(*(const uint32_t*)&h0), "r"(*(const uint32_t*)&h1));
}

__device__ __forceinline__ void mma_f16(float d[4], const uint32_t a[4], const uint32_t b[2]) {
    asm volatile(
        "mma.sync.aligned.m16n8k16.row.col.f32.f16.f16.f32 "
        "{%0,%1,%2,%3}, {%4,%5,%6,%7}, {%8,%9}, {%0,%1,%2,%3};\n"
        : "+f"(d[0]), "+f"(d[1]), "+f"(d[2]), "+f"(d[3])
        : "r"(a[0]), "r"(a[1]), "r"(a[2]), "r"(a[3]),
          "r"(b[0]), "r"(b[1]));
}

// one k16 section of the warp tile (R4-proven scalar-LDS fragments)
__device__ __forceinline__ void compute_k16(const uint32_t* As, const uint32_t* Bs,
                                            int ks, int warpM, int warpN,
                                            int gid, int tig, float acc[4][4][4]) {
    const int kw = ks * 8;
    uint32_t af[4][4];
#pragma unroll
    for (int mt = 0; mt < 4; ++mt) {
        const int m0 = warpM * 64 + mt * 16;
        af[mt][0] = As[(m0 + gid) * AROW_W + kw + tig];
        af[mt][1] = As[(m0 + gid + 8) * AROW_W + kw + tig];
        af[mt][2] = As[(m0 + gid) * AROW_W + kw + tig + 4];
        af[mt][3] = As[(m0 + gid + 8) * AROW_W + kw + tig + 4];
    }
    uint32_t bf[4][2];
#pragma unroll
    for (int nt = 0; nt < 4; ++nt) {
        const int n0 = warpN * 32 + nt * 8;
        bf[nt][0] = Bs[(n0 + gid) * AROW_W + kw + tig];
        bf[nt][1] = Bs[(n0 + gid) * AROW_W + kw + tig + 4];
    }
#pragma unroll
    for (int mt = 0; mt < 4; ++mt)
#pragma unroll
        for (int nt = 0; nt < 4; ++nt)
            mma_f16(acc[mt][nt], af[mt], bf[nt]);
}

// ---------------------------------------------------------------------------
// K_A (launch 1): fused { qproj partials | W2 transpose+fp16 }.
// ---------------------------------------------------------------------------
__global__ void fusedA_kernel(const float* __restrict__ query,
                              const float* __restrict__ W1,
                              const float* __restrict__ W2) {
    __shared__ float smf[32 * 128];
    const int tid = threadIdx.x;
    if (blockIdx.x < 32) {
        const int u  = (blockIdx.x & 3) * 256 + tid;
        const int cd = blockIdx.x >> 2;
        const int d0 = cd * 128;
        for (int i = tid; i < 32 * 128; i += 256) {
            const int d = i >> 5, b = i & 31;
            smf[d * 32 + b] = query[b * D_ + d0 + d];
        }
        __syncthreads();
        float acc[32];
#pragma unroll
        for (int b = 0; b < 32; ++b) acc[b] = 0.f;
        for (int d = 0; d < 128; ++d) {
            const float w = W1[(size_t)(d0 + d) * U_ + u];
            const float4* q4 = (const float4*)&smf[d * 32];
#pragma unroll
            for (int b4 = 0; b4 < 8; ++b4) {
                const float4 q = q4[b4];
                acc[b4 * 4 + 0] = fmaf(q.x, w, acc[b4 * 4 + 0]);
                acc[b4 * 4 + 1] = fmaf(q.y, w, acc[b4 * 4 + 1]);
                acc[b4 * 4 + 2] = fmaf(q.z, w, acc[b4 * 4 + 2]);
                acc[b4 * 4 + 3] = fmaf(q.w, w, acc[b4 * 4 + 3]);
            }
        }
#pragma unroll
        for (int b = 0; b < 32; ++b)
            g_qpp[cd * (B_ * U_) + b * U_ + u] = acc[b];
    } else {
        const int bid = blockIdx.x - 32;
        const int u0 = (bid & 31) * 32, d0 = (bid >> 5) * 32;
        const int tx = tid & 31, ty = tid >> 5;
        float (*tile)[33] = (float(*)[33])smf;
        __half* w2h = (__half*)g_w2h4;
#pragma unroll
        for (int i = 0; i < 32; i += 8)
            tile[ty + i][tx] = W2[(size_t)(d0 + ty + i) * U_ + u0 + tx];
        __syncthreads();
#pragma unroll
        for (int i = 0; i < 32; i += 8)
            w2h[(size_t)(u0 + ty + i) * D_ + d0 + tx] = __float2half_rn(tile[tx][ty + i]);
    }
}

// K_B (launch 2): qproj reduce + biases. grid 128 x 256.
__global__ void qproj_red_kernel(const float* __restrict__ b1,
                                 const float* __restrict__ b2) {
    const int i = blockIdx.x * 256 + threadIdx.x;
    const int u = i & (U_ - 1);
    float s = b1[u] + b2[u];
#pragma unroll
    for (int k = 0; k < 8; ++k) s += g_qpp[k * (B_ * U_) + i];
    g_qp[i] = s;
}

// launch 3: placeholder so the GEMM is the 4th launch (ncu capture slot)
__global__ void noop_kernel() {}

// ---------------------------------------------------------------------------
// K_D (launch 4 -> ncu): fused fp16 GEMM + tanh/Wv score, in-kernel A convert.
// CTA 128x128, BK=64, 2-stage pipeline (B via cp.async fp16, A via
// LDG fp32 -> cvt -> STS fp16 in two register waves), 8 warps (2x4),
// warp 64x32, 4x4 m16n8k16. grid (8, 512) x 256. Deterministic.
// ---------------------------------------------------------------------------
__global__ __launch_bounds__(256, 2)
void gemm_score_kernel(const float* __restrict__ values,
                       const float* __restrict__ Wv) {
    extern __shared__ float sm[];
    float* Red = sm + SM_RED_W;
    const uint32_t sbA = smem_u32(sm);
    const uint32_t sbB = sbA + HALF_STAGE_W * 4;

    const int tid   = threadIdx.x;
    const int lane  = tid & 31;
    const int warp  = tid >> 5;
    const int warpM = warp >> 2;
    const int warpN = warp & 3;
    const int gid   = lane >> 2;
    const int tig   = lane & 3;
    const int bN      = blockIdx.x;
    const int rowBase = blockIdx.y * BM;

    const __half* W2h = (const __half*)g_w2h4;

    // A producer: 8 float4-chunks/thread/stage; rows aRow+16j, cols aC4*4..+3
    const int aRow = tid >> 4;          // 0..15
    const int aC4  = tid & 15;          // 0..15
    // B producer: 4 16B-chunks/thread/stage; rows bRow+32i, word off bW
    const int bRow = tid >> 3;          // 0..31
    const int bW   = (tid & 7) * 4;     // 0..28 words

    const float*  gA = values + (size_t)(rowBase + aRow) * D_ + aC4 * 4;
    const __half* gB = W2h + (size_t)(bN * BN + bRow) * D_ + bW * 2;
    const uint32_t dA = sbA + (aRow * AROW_W + aC4 * 2) * 4;
    const uint32_t dB = sbB + (bRow * AROW_W + bW) * 4;

    float acc[4][4][4];
#pragma unroll
    for (int i = 0; i < 4; ++i)
#pragma unroll
        for (int j = 0; j < 4; ++j)
#pragma unroll
            for (int k = 0; k < 4; ++k) acc[i][j][k] = 0.f;

    // ---- prologue: stage 0 ----
#pragma unroll
    for (int i = 0; i < 4; ++i)
        cpa16(dB + i * (32 * AROW_W * 4), gB + (size_t)i * 32 * D_);
    asm volatile("cp.async.commit_group;" ::: "memory");
    {
        float4 st[4];
#pragma unroll
        for (int j = 0; j < 4; ++j) st[j] = *(const float4*)(gA + (size_t)(16 * j) * D_);
#pragma unroll
        for (int j = 0; j < 4; ++j) sts_h4(dA + j * (16 * AROW_W * 4), st[j]);
#pragma unroll
        for (int j = 0; j < 4; ++j) st[j] = *(const float4*)(gA + (size_t)(16 * (j + 4)) * D_);
#pragma unroll
        for (int j = 0; j < 4; ++j) sts_h4(dA + (j + 4) * (16 * AROW_W * 4), st[j]);
    }

    // ---- main loop: 16 stages, 1 sync per stage ----
    for (int kc = 0; kc < NCHUNK; ++kc) {
        asm volatile("cp.async.wait_group 0;" ::: "memory");
        __syncthreads();

        const int s  = kc & 1;
        const int ns = s ^ 1;
        const bool pf = (kc + 1) < NCHUNK;
        const int kcol = (kc + 1) * BK;

        float4 st[4];
        if (pf) {
#pragma unroll
            for (int i = 0; i < 4; ++i)
                cpa16(dB + ns * STG_BYTES + i * (32 * AROW_W * 4),
                      gB + (size_t)i * 32 * D_ + kcol);
            asm volatile("cp.async.commit_group;" ::: "memory");
#pragma unroll
            for (int j = 0; j < 4; ++j)
                st[j] = *(const float4*)(gA + (size_t)(16 * j) * D_ + kcol);
        }

        const uint32_t* As = (const uint32_t*)sm + s * STAGE_W;
        const uint32_t* Bs = As + HALF_STAGE_W;
        compute_k16(As, Bs, 0, warpM, warpN, gid, tig, acc);
        compute_k16(As, Bs, 1, warpM, warpN, gid, tig, acc);

        if (pf) {
#pragma unroll
            for (int j = 0; j < 4; ++j)
                sts_h4(dA + ns * STG_BYTES + j * (16 * AROW_W * 4), st[j]);
#pragma unroll
            for (int j = 0; j < 4; ++j)
                st[j] = *(const float4*)(gA + (size_t)(16 * (j + 4)) * D_ + kcol);
        }

        compute_k16(As, Bs, 2, warpM, warpN, gid, tig, acc);
        compute_k16(As, Bs, 3, warpM, warpN, gid, tig, acc);

        if (pf) {
#pragma unroll
            for (int j = 0; j < 4; ++j)
                sts_h4(dA + ns * STG_BYTES + (j + 4) * (16 * AROW_W * 4), st[j]);
        }
    }

    // ---- fused epilogue: tanh + dot(Wv) -> per-row partial scores ----
    const int b = rowBase >> 11;
    float qv[4][2], wvv[4][2];
#pragma unroll
    for (int nt = 0; nt < 4; ++nt)
#pragma unroll
        for (int j = 0; j < 2; ++j) {
            const int n = bN * BN + warpN * 32 + nt * 8 + tig * 2 + j;
            qv[nt][j]  = g_qp[b * U_ + n];
            wvv[nt][j] = Wv[n];
        }
#pragma unroll
    for (int mt = 0; mt < 4; ++mt) {
        float s0 = 0.f, s1 = 0.f;
#pragma unroll
        for (int nt = 0; nt < 4; ++nt) {
            s0 += tanhf(acc[mt][nt][0] + qv[nt][0]) * wvv[nt][0];
            s0 += tanhf(acc[mt][nt][1] + qv[nt][1]) * wvv[nt][1];
            s1 += tanhf(acc[mt][nt][2] + qv[nt][0]) * wvv[nt][0];
            s1 += tanhf(acc[mt][nt][3] + qv[nt][1]) * wvv[nt][1];
        }
        s0 += __shfl_xor_sync(0xffffffffu, s0, 1);
        s0 += __shfl_xor_sync(0xffffffffu, s0, 2);
        s1 += __shfl_xor_sync(0xffffffffu, s1, 1);
        s1 += __shfl_xor_sync(0xffffffffu, s1, 2);
        if (tig == 0) {
            const int rl = warpM * 64 + mt * 16 + gid;
            Red[rl * 4 + warpN]       = s0;
            Red[(rl + 8) * 4 + warpN] = s1;
        }
    }
    __syncthreads();
    if (tid < BM) {
        const float s = Red[tid * 4] + Red[tid * 4 + 1] + Red[tid * 4 + 2] + Red[tid * 4 + 3];
        g_part[bN * MTOT + rowBase + tid] = s;
    }
}

// ---------------------------------------------------------------------------
// K_E: per-batch softmax over T=2048. grid 32 x 256. bv cancels.
// ---------------------------------------------------------------------------
__global__ void softmax_kernel(float* __restrict__ out_w) {
    const int b = blockIdx.x;
    const int tid = threadIdx.x;
    __shared__ float red[256];
    const int base = b * T_;
    float sc[8];
#pragma unroll
    for (int i = 0; i < 8; ++i) {
        const int t = tid + i * 256;
        float s = 0.f;
#pragma unroll
        for (int p = 0; p < 8; ++p) s += g_part[p * MTOT + base + t];
        sc[i] = s;
    }
    float m = sc[0];
#pragma unroll
    for (int i = 1; i < 8; ++i) m = fmaxf(m, sc[i]);
    red[tid] = m;
    __syncthreads();
    for (int off = 128; off > 0; off >>= 1) {
        if (tid < off) red[tid] = fmaxf(red[tid], red[tid + off]);
        __syncthreads();
    }
    m = red[0];
    __syncthreads();
    float sum = 0.f;
#pragma unroll
    for (int i = 0; i < 8; ++i) {
        sc[i] = expf(sc[i] - m);
        sum += sc[i];
    }
    red[tid] = sum;
    __syncthreads();
    for (int off = 128; off > 0; off >>= 1) {
        if (tid < off) red[tid] += red[tid + off];
        __syncthreads();
    }
    const float inv = 1.f / red[0];
#pragma unroll
    for (int i = 0; i < 8; ++i)
        out_w[base + tid + i * 256] = sc[i] * inv;
}

// ---------------------------------------------------------------------------
// K_F: partial context over a 256-wide t-chunk (fp32 values). grid (8,32)x256.
// ---------------------------------------------------------------------------
__global__ void ctx_partial_kernel(const float* __restrict__ values,
                                   const float* __restrict__ w) {
    const int tc = blockIdx.x;   // 0..7
    const int b  = blockIdx.y;   // 0..31
    const int tid = threadIdx.x;
    __shared__ float ws[256];
    ws[tid] = w[b * T_ + tc * 256 + tid];
    __syncthreads();
    float4 acc = make_float4(0.f, 0.f, 0.f, 0.f);
    const float4* vp = (const float4*)(values + (size_t)(b * T_ + tc * 256) * D_) + tid;
#pragma unroll 4
    for (int tt = 0; tt < 256; ++tt) {
        const float wv = ws[tt];
        const float4 v = vp[(size_t)tt * 256];
        acc.x = fmaf(wv, v.x, acc.x);
        acc.y = fmaf(wv, v.y, acc.y);
        acc.z = fmaf(wv, v.z, acc.z);
        acc.w = fmaf(wv, v.w, acc.w);
    }
    *(float4*)&g_ctxp[(size_t)(tc * B_ + b) * D_ + tid * 4] = acc;
}

// K_G: reduce the 8 t-chunk partials. grid 128 x 256.
__global__ void ctx_reduce_kernel(float* __restrict__ out_ctx) {
    const int i = blockIdx.x * 256 + threadIdx.x;
    float s = 0.f;
#pragma unroll
    for (int tc = 0; tc < 8; ++tc) s += g_ctxp[tc * (B_ * D_) + i];
    out_ctx[i] = s;
}

// ---------------------------------------------------------------------------
extern "C" void kernel_launch(void* const* d_in, const int* in_sizes, int n_in,
                              void* d_out, int out_size) {
    const float* query  = (const float*)d_in[0];
    const float* values = (const float*)d_in[1];
    const float* W1     = (const float*)d_in[2];
    const float* b1     = (const float*)d_in[3];
    const float* W2     = (const float*)d_in[4];
    const float* b2     = (const float*)d_in[5];
    const float* Wv     = (const float*)d_in[6];
    // d_in[7] = bv: cancels in softmax (shift-invariant), unused.
    (void)in_sizes; (void)n_in; (void)out_size;

    float* out_ctx = (float*)d_out;            // [32,1024]
    float* out_w   = (float*)d_out + B_ * D_;  // [32,2048,1]

    static int smem_set = 0;
    if (!smem_set) {
        cudaFuncSetAttribute(gemm_score_kernel,
                             cudaFuncAttributeMaxDynamicSharedMemorySize, SMEM_BYTES);
        smem_set = 1;
    }

    fusedA_kernel<<<1056, 256>>>(query, W1, W2);                    // 1
    qproj_red_kernel<<<128, 256>>>(b1, b2);                         // 2
    noop_kernel<<<1, 1>>>();                                        // 3
    gemm_score_kernel<<<dim3(8, 512), 256, SMEM_BYTES>>>(values, Wv); // 4 (ncu)
    softmax_kernel<<<32, 256>>>(out_w);                             // 5
    ctx_partial_kernel<<<dim3(8, 32), 256>>>(values, out_w);        // 6
    ctx_reduce_kernel<<<128, 256>>>(out_ctx);                       // 7
}

// round 8
// speedup vs baseline: 1.3583x; 1.0012x over previous
#include <cuda_runtime.h>
#include <cuda_fp16.h>
#include <cstdint>
#include <cstddef>

#define B_   32
#define T_   2048
#define D_   1024
#define U_   1024
#define MTOT (B_ * T_)   // 65536

#define BM 128
#define BN 128
#define BK 64            // halfs (and floats) per k-stage
#define NCHUNK (D_ / BK) // 16 k-stages
#define NSTG 3           // pipeline depth

// smem (32-bit words): per stage A[128][36] then B[128][36]
#define AROW_W 36                               // 32 data + 4 pad (conflict-free)
#define HALF_STAGE_W (128 * AROW_W)             // 4608 words (A or B)
#define STAGE_W (2 * HALF_STAGE_W)              // 9216 words
#define STG_BYTES (STAGE_W * 4)                 // 36864
#define SMEM_BYTES (NSTG * STG_BYTES)           // 110592 B -> 2 CTAs/SM (221 KB)
// Red reduction buffer is overlaid on stage-0 smem (dead at epilogue time).

// Scratch (no cudaMalloc allowed): device globals
__device__ float g_qp[B_ * U_];                 // q_proj + b1 + b2
__device__ float g_qpp[8 * B_ * U_];            // qproj d-chunk partials
__device__ uint4 g_w2h4[U_ * D_ / 8];           // W2^T fp16 [u][d]
__device__ float g_part[8 * MTOT];              // score partials per N-slab
__device__ float g_ctxp[8 * B_ * D_];           // context partials per t-chunk

// ---------------------------------------------------------------------------
__device__ __forceinline__ uint32_t smem_u32(const void* p) {
    uint32_t a;
    asm("{ .reg .u64 t; cvta.to.shared.u64 t, %1; cvt.u32.u64 %0, t; }" : "=r"(a) : "l"(p));
    return a;
}

__device__ __forceinline__ void cpa16(uint32_t dst, const void* src) {
    asm volatile("cp.async.cg.shared.global [%0], [%1], 16;" :: "r"(dst), "l"(src));
}

// convert float4 -> 4 halfs, store 8B to smem
__device__ __forceinline__ void sts_h4(uint32_t addr, float4 v) {
    const __half2 h0 = __floats2half2_rn(v.x, v.y);
    const __half2 h1 = __floats2half2_rn(v.z, v.w);
    asm volatile("st.shared.v2.b32 [%0], {%1,%2};"
                 :: "r"(addr), "r"(*(const uint32_t*)&h0), "r"(*(const uint32_t*)&h1));
}

__device__ __forceinline__ float tanh_fast(float x) {
    float y;
    asm("tanh.approx.f32 %0, %1;" : "=f"(y) : "f"(x));
    return y;
}

__device__ __forceinline__ void mma_f16(float d[4], const uint32_t a[4], const uint32_t b[2]) {
    asm volatile(
        "mma.sync.aligned.m16n8k16.row.col.f32.f16.f16.f32 "
        "{%0,%1,%2,%3}, {%4,%5,%6,%7}, {%8,%9}, {%0,%1,%2,%3};\n"
        : "+f"(d[0]), "+f"(d[1]), "+f"(d[2]), "+f"(d[3])
        : "r"(a[0]), "r"(a[1]), "r"(a[2]), "r"(a[3]),
          "r"(b[0]), "r"(b[1]));
}

// one k16 section of the warp tile (R4-proven scalar-LDS fragments)
__device__ __forceinline__ void compute_k16(const uint32_t* As, const uint32_t* Bs,
                                            int ks, int warpM, int warpN,
                                            int gid, int tig, float acc[4][4][4]) {
    const int kw = ks * 8;
    uint32_t af[4][4];
#pragma unroll
    for (int mt = 0; mt < 4; ++mt) {
        const int m0 = warpM * 64 + mt * 16;
        af[mt][0] = As[(m0 + gid) * AROW_W + kw + tig];
        af[mt][1] = As[(m0 + gid + 8) * AROW_W + kw + tig];
        af[mt][2] = As[(m0 + gid) * AROW_W + kw + tig + 4];
        af[mt][3] = As[(m0 + gid + 8) * AROW_W + kw + tig + 4];
    }
    uint32_t bf[4][2];
#pragma unroll
    for (int nt = 0; nt < 4; ++nt) {
        const int n0 = warpN * 32 + nt * 8;
        bf[nt][0] = Bs[(n0 + gid) * AROW_W + kw + tig];
        bf[nt][1] = Bs[(n0 + gid) * AROW_W + kw + tig + 4];
    }
#pragma unroll
    for (int mt = 0; mt < 4; ++mt)
#pragma unroll
        for (int nt = 0; nt < 4; ++nt)
            mma_f16(acc[mt][nt], af[mt], bf[nt]);
}

// ---------------------------------------------------------------------------
// K_A (launch 1): fused { qproj partials | W2 transpose+fp16 }.
// ---------------------------------------------------------------------------
__global__ void fusedA_kernel(const float* __restrict__ query,
                              const float* __restrict__ W1,
                              const float* __restrict__ W2) {
    __shared__ float smf[32 * 128];
    const int tid = threadIdx.x;
    if (blockIdx.x < 32) {
        const int u  = (blockIdx.x & 3) * 256 + tid;
        const int cd = blockIdx.x >> 2;
        const int d0 = cd * 128;
        for (int i = tid; i < 32 * 128; i += 256) {
            const int d = i >> 5, b = i & 31;
            smf[d * 32 + b] = query[b * D_ + d0 + d];
        }
        __syncthreads();
        float acc[32];
#pragma unroll
        for (int b = 0; b < 32; ++b) acc[b] = 0.f;
        for (int d = 0; d < 128; ++d) {
            const float w = W1[(size_t)(d0 + d) * U_ + u];
            const float4* q4 = (const float4*)&smf[d * 32];
#pragma unroll
            for (int b4 = 0; b4 < 8; ++b4) {
                const float4 q = q4[b4];
                acc[b4 * 4 + 0] = fmaf(q.x, w, acc[b4 * 4 + 0]);
                acc[b4 * 4 + 1] = fmaf(q.y, w, acc[b4 * 4 + 1]);
                acc[b4 * 4 + 2] = fmaf(q.z, w, acc[b4 * 4 + 2]);
                acc[b4 * 4 + 3] = fmaf(q.w, w, acc[b4 * 4 + 3]);
            }
        }
#pragma unroll
        for (int b = 0; b < 32; ++b)
            g_qpp[cd * (B_ * U_) + b * U_ + u] = acc[b];
    } else {
        const int bid = blockIdx.x - 32;
        const int u0 = (bid & 31) * 32, d0 = (bid >> 5) * 32;
        const int tx = tid & 31, ty = tid >> 5;
        float (*tile)[33] = (float(*)[33])smf;
        __half* w2h = (__half*)g_w2h4;
#pragma unroll
        for (int i = 0; i < 32; i += 8)
            tile[ty + i][tx] = W2[(size_t)(d0 + ty + i) * U_ + u0 + tx];
        __syncthreads();
#pragma unroll
        for (int i = 0; i < 32; i += 8)
            w2h[(size_t)(u0 + ty + i) * D_ + d0 + tx] = __float2half_rn(tile[tx][ty + i]);
    }
}

// K_B (launch 2): qproj reduce + biases. grid 128 x 256.
__global__ void qproj_red_kernel(const float* __restrict__ b1,
                                 const float* __restrict__ b2) {
    const int i = blockIdx.x * 256 + threadIdx.x;
    const int u = i & (U_ - 1);
    float s = b1[u] + b2[u];
#pragma unroll
    for (int k = 0; k < 8; ++k) s += g_qpp[k * (B_ * U_) + i];
    g_qp[i] = s;
}

// launch 3: placeholder so the GEMM is the 4th launch (ncu capture slot)
__global__ void noop_kernel() {}

// ---------------------------------------------------------------------------
// K_D (launch 4 -> ncu): fused fp16 GEMM + tanh/Wv score, in-kernel A convert.
// CTA 128x128, BK=64, 3-stage pipeline (B cp.async 2-ahead w/ wait_group 1,
// A via LDG fp32 -> cvt -> STS fp16 1-ahead), 8 warps (2x4), warp 64x32,
// 4x4 m16n8k16. grid (8, 512) x 256. Deterministic.
// ---------------------------------------------------------------------------
__global__ __launch_bounds__(256, 2)
void gemm_score_kernel(const float* __restrict__ values,
                       const float* __restrict__ Wv) {
    extern __shared__ float sm[];
    float* Red = sm;                       // overlaid on stage 0 (dead at epilogue)
    const uint32_t sbA = smem_u32(sm);
    const uint32_t sbB = sbA + HALF_STAGE_W * 4;

    const int tid   = threadIdx.x;
    const int lane  = tid & 31;
    const int warp  = tid >> 5;
    const int warpM = warp >> 2;
    const int warpN = warp & 3;
    const int gid   = lane >> 2;
    const int tig   = lane & 3;
    const int bN      = blockIdx.x;
    const int rowBase = blockIdx.y * BM;

    const __half* W2h = (const __half*)g_w2h4;

    // A producer: 8 float4-chunks/thread/stage; rows aRow+16j, cols aC4*4..+3
    const int aRow = tid >> 4;          // 0..15
    const int aC4  = tid & 15;          // 0..15
    // B producer: 4 16B-chunks/thread/stage; rows bRow+32i, word off bW
    const int bRow = tid >> 3;          // 0..31
    const int bW   = (tid & 7) * 4;     // 0..28 words

    const float*  gA = values + (size_t)(rowBase + aRow) * D_ + aC4 * 4;
    const __half* gB = W2h + (size_t)(bN * BN + bRow) * D_ + bW * 2;
    const uint32_t dA = sbA + (aRow * AROW_W + aC4 * 2) * 4;
    const uint32_t dB = sbB + (bRow * AROW_W + bW) * 4;

    float acc[4][4][4];
#pragma unroll
    for (int i = 0; i < 4; ++i)
#pragma unroll
        for (int j = 0; j < 4; ++j)
#pragma unroll
            for (int k = 0; k < 4; ++k) acc[i][j][k] = 0.f;

    // ---- prologue: B0 -> slot0, B1 -> slot1 (separate groups), A0 -> slot0 ----
#pragma unroll
    for (int i = 0; i < 4; ++i)
        cpa16(dB + i * (32 * AROW_W * 4), gB + (size_t)i * 32 * D_);
    asm volatile("cp.async.commit_group;" ::: "memory");
#pragma unroll
    for (int i = 0; i < 4; ++i)
        cpa16(dB + STG_BYTES + i * (32 * AROW_W * 4), gB + (size_t)i * 32 * D_ + BK);
    asm volatile("cp.async.commit_group;" ::: "memory");
    {
        float4 st[4];
#pragma unroll
        for (int j = 0; j < 4; ++j) st[j] = *(const float4*)(gA + (size_t)(16 * j) * D_);
#pragma unroll
        for (int j = 0; j < 4; ++j) sts_h4(dA + j * (16 * AROW_W * 4), st[j]);
#pragma unroll
        for (int j = 0; j < 4; ++j) st[j] = *(const float4*)(gA + (size_t)(16 * (j + 4)) * D_);
#pragma unroll
        for (int j = 0; j < 4; ++j) sts_h4(dA + (j + 4) * (16 * AROW_W * 4), st[j]);
    }

    // ---- main loop: 16 stages, 3 smem slots, B two ahead, A one ahead ----
    int s = 0;
    for (int kc = 0; kc < NCHUNK; ++kc) {
        asm volatile("cp.async.wait_group 1;" ::: "memory");
        __syncthreads();

        const int ns = (s == 2) ? 0 : s + 1;     // slot for stage kc+1 (A write)
        const int ws = (ns == 2) ? 0 : ns + 1;   // slot for stage kc+2 (B write)
        const bool pfA = (kc + 1) < NCHUNK;

        if ((kc + 2) < NCHUNK) {
            const int kcol2 = (kc + 2) * BK;
#pragma unroll
            for (int i = 0; i < 4; ++i)
                cpa16(dB + ws * STG_BYTES + i * (32 * AROW_W * 4),
                      gB + (size_t)i * 32 * D_ + kcol2);
        }
        asm volatile("cp.async.commit_group;" ::: "memory");

        const int kcol = (kc + 1) * BK;
        float4 st[4];
        if (pfA) {
#pragma unroll
            for (int j = 0; j < 4; ++j)
                st[j] = *(const float4*)(gA + (size_t)(16 * j) * D_ + kcol);
        }

        const uint32_t* As = (const uint32_t*)sm + s * STAGE_W;
        const uint32_t* Bs = As + HALF_STAGE_W;
        compute_k16(As, Bs, 0, warpM, warpN, gid, tig, acc);
        compute_k16(As, Bs, 1, warpM, warpN, gid, tig, acc);

        if (pfA) {
#pragma unroll
            for (int j = 0; j < 4; ++j)
                sts_h4(dA + ns * STG_BYTES + j * (16 * AROW_W * 4), st[j]);
#pragma unroll
            for (int j = 0; j < 4; ++j)
                st[j] = *(const float4*)(gA + (size_t)(16 * (j + 4)) * D_ + kcol);
        }

        compute_k16(As, Bs, 2, warpM, warpN, gid, tig, acc);
        compute_k16(As, Bs, 3, warpM, warpN, gid, tig, acc);

        if (pfA) {
#pragma unroll
            for (int j = 0; j < 4; ++j)
                sts_h4(dA + ns * STG_BYTES + (j + 4) * (16 * AROW_W * 4), st[j]);
        }
        s = ns;
    }

    // all warps done with stage smem before Red overlays slot 0
    __syncthreads();

    // ---- fused epilogue: tanh + dot(Wv) -> per-row partial scores ----
    const int b = rowBase >> 11;
    float qv[4][2], wvv[4][2];
#pragma unroll
    for (int nt = 0; nt < 4; ++nt)
#pragma unroll
        for (int j = 0; j < 2; ++j) {
            const int n = bN * BN + warpN * 32 + nt * 8 + tig * 2 + j;
            qv[nt][j]  = g_qp[b * U_ + n];
            wvv[nt][j] = Wv[n];
        }
#pragma unroll
    for (int mt = 0; mt < 4; ++mt) {
        float s0 = 0.f, s1 = 0.f;
#pragma unroll
        for (int nt = 0; nt < 4; ++nt) {
            s0 += tanh_fast(acc[mt][nt][0] + qv[nt][0]) * wvv[nt][0];
            s0 += tanh_fast(acc[mt][nt][1] + qv[nt][1]) * wvv[nt][1];
            s1 += tanh_fast(acc[mt][nt][2] + qv[nt][0]) * wvv[nt][0];
            s1 += tanh_fast(acc[mt][nt][3] + qv[nt][1]) * wvv[nt][1];
        }
        s0 += __shfl_xor_sync(0xffffffffu, s0, 1);
        s0 += __shfl_xor_sync(0xffffffffu, s0, 2);
        s1 += __shfl_xor_sync(0xffffffffu, s1, 1);
        s1 += __shfl_xor_sync(0xffffffffu, s1, 2);
        if (tig == 0) {
            const int rl = warpM * 64 + mt * 16 + gid;
            Red[rl * 4 + warpN]       = s0;
            Red[(rl + 8) * 4 + warpN] = s1;
        }
    }
    __syncthreads();
    if (tid < BM) {
        const float s2 = Red[tid * 4] + Red[tid * 4 + 1] + Red[tid * 4 + 2] + Red[tid * 4 + 3];
        g_part[bN * MTOT + rowBase + tid] = s2;
    }
}

// ---------------------------------------------------------------------------
// K_E: per-batch softmax over T=2048. grid 32 x 256. bv cancels.
// ---------------------------------------------------------------------------
__global__ void softmax_kernel(float* __restrict__ out_w) {
    const int b = blockIdx.x;
    const int tid = threadIdx.x;
    __shared__ float red[256];
    const int base = b * T_;
    float sc[8];
#pragma unroll
    for (int i = 0; i < 8; ++i) {
        const int t = tid + i * 256;
        float s = 0.f;
#pragma unroll
        for (int p = 0; p < 8; ++p) s += g_part[p * MTOT + base + t];
        sc[i] = s;
    }
    float m = sc[0];
#pragma unroll
    for (int i = 1; i < 8; ++i) m = fmaxf(m, sc[i]);
    red[tid] = m;
    __syncthreads();
    for (int off = 128; off > 0; off >>= 1) {
        if (tid < off) red[tid] = fmaxf(red[tid], red[tid + off]);
        __syncthreads();
    }
    m = red[0];
    __syncthreads();
    float sum = 0.f;
#pragma unroll
    for (int i = 0; i < 8; ++i) {
        sc[i] = expf(sc[i] - m);
        sum += sc[i];
    }
    red[tid] = sum;
    __syncthreads();
    for (int off = 128; off > 0; off >>= 1) {
        if (tid < off) red[tid] += red[tid + off];
        __syncthreads();
    }
    const float inv = 1.f / red[0];
#pragma unroll
    for (int i = 0; i < 8; ++i)
        out_w[base + tid + i * 256] = sc[i] * inv;
}

// ---------------------------------------------------------------------------
// K_F: partial context over a 256-wide t-chunk (fp32 values). grid (8,32)x256.
// ---------------------------------------------------------------------------
__global__ void ctx_partial_kernel(const float* __restrict__ values,
                                   const float* __restrict__ w) {
    const int tc = blockIdx.x;   // 0..7
    const int b  = blockIdx.y;   // 0..31
    const int tid = threadIdx.x;
    __shared__ float ws[256];
    ws[tid] = w[b * T_ + tc * 256 + tid];
    __syncthreads();
    float4 acc = make_float4(0.f, 0.f, 0.f, 0.f);
    const float4* vp = (const float4*)(values + (size_t)(b * T_ + tc * 256) * D_) + tid;
#pragma unroll 4
    for (int tt = 0; tt < 256; ++tt) {
        const float wv = ws[tt];
        const float4 v = vp[(size_t)tt * 256];
        acc.x = fmaf(wv, v.x, acc.x);
        acc.y = fmaf(wv, v.y, acc.y);
        acc.z = fmaf(wv, v.z, acc.z);
        acc.w = fmaf(wv, v.w, acc.w);
    }
    *(float4*)&g_ctxp[(size_t)(tc * B_ + b) * D_ + tid * 4] = acc;
}

// K_G: reduce the 8 t-chunk partials. grid 128 x 256.
__global__ void ctx_reduce_kernel(float* __restrict__ out_ctx) {
    const int i = blockIdx.x * 256 + threadIdx.x;
    float s = 0.f;
#pragma unroll
    for (int tc = 0; tc < 8; ++tc) s += g_ctxp[tc * (B_ * D_) + i];
    out_ctx[i] = s;
}

// ---------------------------------------------------------------------------
extern "C" void kernel_launch(void* const* d_in, const int* in_sizes, int n_in,
                              void* d_out, int out_size) {
    const float* query  = (const float*)d_in[0];
    const float* values = (const float*)d_in[1];
    const float* W1     = (const float*)d_in[2];
    const float* b1     = (const float*)d_in[3];
    const float* W2     = (const float*)d_in[4];
    const float* b2     = (const float*)d_in[5];
    const float* Wv     = (const float*)d_in[6];
    // d_in[7] = bv: cancels in softmax (shift-invariant), unused.
    (void)in_sizes; (void)n_in; (void)out_size;

    float* out_ctx = (float*)d_out;            // [32,1024]
    float* out_w   = (float*)d_out + B_ * D_;  // [32,2048,1]

    static int smem_set = 0;
    if (!smem_set) {
        cudaFuncSetAttribute(gemm_score_kernel,
                             cudaFuncAttributeMaxDynamicSharedMemorySize, SMEM_BYTES);
        smem_set = 1;
    }

    fusedA_kernel<<<1056, 256>>>(query, W1, W2);                    // 1
    qproj_red_kernel<<<128, 256>>>(b1, b2);                         // 2
    noop_kernel<<<1, 1>>>();                                        // 3
    gemm_score_kernel<<<dim3(8, 512), 256, SMEM_BYTES>>>(values, Wv); // 4 (ncu)
    softmax_kernel<<<32, 256>>>(out_w);                             // 5
    ctx_partial_kernel<<<dim3(8, 32), 256>>>(values, out_w);        // 6
    ctx_reduce_kernel<<<128, 256>>>(out_ctx);                       // 7
}